// round 12
// baseline (speedup 1.0000x reference)
#include <cuda_runtime.h>
#include <cuda_bf16.h>
#include <cstdint>

// HMM forward: T=1024, S=512, D=32, K=64 — single warp-specialized kernel.
// 128 CTAs x 256 threads. Warps 4..7 (high wid = arbiter priority): recursion,
// 4 sequences/CTA (R7-proven geometry), A in regs, rescale every 4 steps.
// Warps 0..3: emission (ILP4), 32 tasks each in t-ascending order; each task is
// 32 rows of one t. Producer->consumer via g_cnt[t] (16 arrivals per t),
// acquire-gated prefetches pipelined one chunk ahead. Emission's issue work
// (~135K cyc/SMSP) hides inside recursion's ~80% idle issue slots.

#define HT 1024
#define HS 512
#define HD 32
#define HK 64
#define LOG2PI_F 1.8378770664093453f
#define NEG_HALF_LOG2E -0.72134752044448169f
#define LN2_F 0.69314718055994531f

#define NCTAS 128
#define NTHREADS 256

typedef unsigned long long ull;

__device__ float g_P[(size_t)HT * HS * HK];   // 128 MB normalized emission probs [t][s][k]
__device__ float g_M[(size_t)HT * HS];        // per-(t,s) log2 max
__device__ float g_loglik[HS];
__device__ unsigned int g_cnt[HT];            // ==16 when slab t complete
__device__ unsigned int g_done;

__device__ __forceinline__ void fma2(ull& d, ull a, ull b, ull c) {
    asm("fma.rn.f32x2 %0, %1, %2, %3;" : "=l"(d) : "l"(a), "l"(b), "l"(c));
}
__device__ __forceinline__ void add2(ull& d, ull a, ull b) {
    asm("add.rn.f32x2 %0, %1, %2;" : "=l"(d) : "l"(a), "l"(b));
}
__device__ __forceinline__ void mul2(ull& d, ull a, ull b) {
    asm("mul.rn.f32x2 %0, %1, %2;" : "=l"(d) : "l"(a), "l"(b));
}
__device__ __forceinline__ ull pk2(float lo, float hi) {
    ull r;
    asm("mov.b64 %0, {%1, %2};" : "=l"(r) : "f"(lo), "f"(hi));
    return r;
}
__device__ __forceinline__ void unpk2(float& lo, float& hi, ull v) {
    asm("mov.b64 {%0, %1}, %2;" : "=f"(lo), "=f"(hi) : "l"(v));
}
__device__ __forceinline__ float ex2a(float x) {
    float r; asm("ex2.approx.f32 %0, %1;" : "=f"(r) : "f"(x)); return r;
}
__device__ __forceinline__ float lg2a(float x) {
    float r; asm("lg2.approx.f32 %0, %1;" : "=f"(r) : "f"(x)); return r;
}
__device__ __forceinline__ float rcpa(float x) {
    float r; asm("rcp.approx.f32 %0, %1;" : "=f"(r) : "f"(x)); return r;
}
__device__ __forceinline__ unsigned int ld_acq(const unsigned int* p) {
    unsigned int v;
    asm volatile("ld.acquire.gpu.global.u32 %0, [%1];" : "=r"(v) : "l"(p));
    return v;
}
__device__ __forceinline__ void wait16(int t) {
    unsigned int v = ld_acq(&g_cnt[t]);
    while (v < 16u) { __nanosleep(128); v = ld_acq(&g_cnt[t]); }
}
__device__ __forceinline__ void embar() {      // barrier for the 4 emission warps only
    asm volatile("bar.sync 1, 128;" ::: "memory");
}

// full-K sum of 32 packed ulls in smem -> scalar (4 chains of 8, no shuffles)
__device__ __forceinline__ float sum_tree(const ull* vb) {
    ull c0 = vb[0], c1 = vb[1], c2 = vb[2], c3 = vb[3];
    #pragma unroll
    for (int j = 1; j < 8; ++j) {
        ull v0 = vb[4 * j], v1 = vb[4 * j + 1], v2 = vb[4 * j + 2], v3 = vb[4 * j + 3];
        add2(c0, c0, v0); add2(c1, c1, v1); add2(c2, c2, v2); add2(c3, c3, v3);
    }
    add2(c0, c0, c1);
    add2(c2, c2, c3);
    add2(c0, c0, c2);
    float lo, hi;
    unpk2(lo, hi, c0);
    return lo + hi;
}

// shared memory layout (one struct so both paths see the same allocation)
struct SmemLayout {
    ull   W1[16][HK];                 // 8KB
    ull   W2[16][HK];                 // 8KB
    float pc[16][HK];                 // 4KB
    float C[HK];                      // 256B
    __align__(16) float sx[4][2][4][HD];   // 4KB emission x staging
    __align__(16) float sv[4][2][HK];      // 2KB recursion state
};

// ==================== emission (warps 0..3) ====================
__device__ void emission_warp(SmemLayout* sm,
                              const float* __restrict__ data,
                              const float* __restrict__ means,
                              const float* __restrict__ covars) {
    int tid  = threadIdx.x;        // 0..127 for emission warps
    int lane = tid & 31;
    int wid  = tid >> 5;           // 0..3
    int e    = blockIdx.x * 4 + wid;   // emission warp id, 0..511

    // cooperative coefficient build (128 em threads)
    #pragma unroll
    for (int it = 0; it < 8; ++it) {
        int idx = it * 128 + tid;
        int k  = idx >> 4;
        int dp = idx & 15;
        float2 cv = *reinterpret_cast<const float2*>(&covars[k * HD + 2 * dp]);
        float2 mu = *reinterpret_cast<const float2*>(&means [k * HD + 2 * dp]);
        float iv0 = 1.0f / cv.x, iv1 = 1.0f / cv.y;
        sm->W1[dp][k] = pk2(NEG_HALF_LOG2E * iv0, NEG_HALF_LOG2E * iv1);
        sm->W2[dp][k] = pk2(NEG_HALF_LOG2E * (-2.0f * mu.x * iv0),
                            NEG_HALF_LOG2E * (-2.0f * mu.y * iv1));
        sm->pc[dp][k] = mu.x * mu.x * iv0 + mu.y * mu.y * iv1 + __logf(cv.x) + __logf(cv.y);
    }
    embar();
    if (tid < HK) {
        float c = (float)HD * LOG2PI_F;
        #pragma unroll
        for (int dp = 0; dp < 16; ++dp) c += sm->pc[dp][tid];
        sm->C[tid] = NEG_HALF_LOG2E * c;
    }
    embar();

    ull w1A[16], w2A[16], w1B[16], w2B[16];
    #pragma unroll
    for (int g = 0; g < 16; ++g) {
        ulonglong2 v1 = *reinterpret_cast<const ulonglong2*>(&sm->W1[g][2 * lane]);
        ulonglong2 v2 = *reinterpret_cast<const ulonglong2*>(&sm->W2[g][2 * lane]);
        w1A[g] = v1.x; w1B[g] = v1.y;
        w2A[g] = v2.x; w2B[g] = v2.y;
    }
    float cA = sm->C[2 * lane], cB = sm->C[2 * lane + 1];

    ull* Pout = reinterpret_cast<ull*>(g_P);

    // 32 tasks, t-ascending: task = m*512 + e  -> t = m*32 + (e>>4)
    for (int m = 0; m < 32; ++m) {
        int task = m * 512 + e;
        int ts0  = task * 32;
        int trow = task >> 4;

        float xg[4];
        #pragma unroll
        for (int j = 0; j < 4; ++j)
            xg[j] = __ldg(&data[(size_t)(ts0 + j) * HD + lane]);
        #pragma unroll
        for (int j = 0; j < 4; ++j)
            sm->sx[wid][0][j][lane] = xg[j];
        #pragma unroll
        for (int j = 0; j < 4; ++j)
            xg[j] = __ldg(&data[(size_t)(ts0 + 4 + j) * HD + lane]);
        __syncwarp();

        for (int gq = 0; gq < 8; ++gq) {
            if (gq < 7) {
                #pragma unroll
                for (int j = 0; j < 4; ++j)
                    sm->sx[wid][(gq + 1) & 1][j][lane] = xg[j];
                if (gq < 6) {
                    #pragma unroll
                    for (int j = 0; j < 4; ++j)
                        xg[j] = __ldg(&data[(size_t)(ts0 + (gq + 2) * 4 + j) * HD + lane]);
                }
            }
            __syncwarp();

            const ull* xb0 = reinterpret_cast<const ull*>(sm->sx[wid][gq & 1][0]);
            const ull* xb1 = reinterpret_cast<const ull*>(sm->sx[wid][gq & 1][1]);
            const ull* xb2 = reinterpret_cast<const ull*>(sm->sx[wid][gq & 1][2]);
            const ull* xb3 = reinterpret_cast<const ull*>(sm->sx[wid][gq & 1][3]);

            ull accA[4], accB[4];
            #pragma unroll
            for (int r = 0; r < 4; ++r) { accA[r] = 0ULL; accB[r] = 0ULL; }

            #pragma unroll
            for (int g = 0; g < 16; ++g) {
                ull x0 = xb0[g], x1 = xb1[g], x2 = xb2[g], x3 = xb3[g];
                ull t;
                fma2(t, x0, w1A[g], w2A[g]); fma2(accA[0], x0, t, accA[0]);
                fma2(t, x0, w1B[g], w2B[g]); fma2(accB[0], x0, t, accB[0]);
                fma2(t, x1, w1A[g], w2A[g]); fma2(accA[1], x1, t, accA[1]);
                fma2(t, x1, w1B[g], w2B[g]); fma2(accB[1], x1, t, accB[1]);
                fma2(t, x2, w1A[g], w2A[g]); fma2(accA[2], x2, t, accA[2]);
                fma2(t, x2, w1B[g], w2B[g]); fma2(accB[2], x2, t, accB[2]);
                fma2(t, x3, w1A[g], w2A[g]); fma2(accA[3], x3, t, accA[3]);
                fma2(t, x3, w1B[g], w2B[g]); fma2(accB[3], x3, t, accB[3]);
            }

            float la[4], lb[4], mm[4];
            #pragma unroll
            for (int r = 0; r < 4; ++r) {
                float a0, a1, b0, b1;
                unpk2(a0, a1, accA[r]);
                unpk2(b0, b1, accB[r]);
                la[r] = (a0 + a1) + cA;
                lb[r] = (b0 + b1) + cB;
                mm[r] = fmaxf(la[r], lb[r]);
            }
            #pragma unroll
            for (int off = 16; off; off >>= 1) {
                #pragma unroll
                for (int r = 0; r < 4; ++r)
                    mm[r] = fmaxf(mm[r], __shfl_xor_sync(0xffffffffu, mm[r], off));
            }
            #pragma unroll
            for (int r = 0; r < 4; ++r) {
                float pa = ex2a(la[r] - mm[r]);
                float pb = ex2a(lb[r] - mm[r]);
                int ts = ts0 + gq * 4 + r;
                Pout[(size_t)ts * 32 + lane] = pk2(pa, pb);
            }
            if (lane == 0)
                *reinterpret_cast<float4*>(&g_M[ts0 + gq * 4]) =
                    make_float4(mm[0], mm[1], mm[2], mm[3]);
            __syncwarp();
        }

        // release this task's contribution to slab trow
        __threadfence();
        __syncwarp();
        if (lane == 0)
            atomicAdd(&g_cnt[trow], 1u);
    }
}

// ==================== recursion (warps 4..7) ====================
#define RC_STEP(T_, RESC_) do {                                                 \
    const ull* vb_ = reinterpret_cast<const ull*>(sm->sv[w][((T_) - 1) & 1]);   \
    float rinv_ = 0.0f, lnd_ = 0.0f;                                            \
    if (RESC_) {                                                                \
        float d_ = sum_tree(vb_);                                               \
        rinv_ = rcpa(d_);                                                       \
        lnd_  = lg2a(d_);                                                       \
    }                                                                           \
    ull c00 = 0ULL, c01 = 0ULL, c02 = 0ULL, c03 = 0ULL;                         \
    ull c10 = 0ULL, c11 = 0ULL, c12 = 0ULL, c13 = 0ULL;                         \
    _Pragma("unroll")                                                           \
    for (int j_ = 0; j_ < 8; ++j_) {                                            \
        ull vv_ = vb_[j_];                                                      \
        fma2(c00, vv_, Ak0[j_], c00);                                           \
        fma2(c10, vv_, Ak1[j_], c10);                                           \
    }                                                                           \
    _Pragma("unroll")                                                           \
    for (int j_ = 8; j_ < 16; ++j_) {                                           \
        ull vv_ = vb_[j_];                                                      \
        fma2(c01, vv_, Ak0[j_], c01);                                           \
        fma2(c11, vv_, Ak1[j_], c11);                                           \
    }                                                                           \
    _Pragma("unroll")                                                           \
    for (int j_ = 16; j_ < 24; ++j_) {                                          \
        ull vv_ = vb_[j_];                                                      \
        fma2(c02, vv_, Ak0[j_], c02);                                           \
        fma2(c12, vv_, Ak1[j_], c12);                                           \
    }                                                                           \
    _Pragma("unroll")                                                           \
    for (int j_ = 24; j_ < 32; ++j_) {                                          \
        ull vv_ = vb_[j_];                                                      \
        fma2(c03, vv_, Ak0[j_], c03);                                           \
        fma2(c13, vv_, Ak1[j_], c13);                                           \
    }                                                                           \
    add2(c00, c00, c01); add2(c02, c02, c03); add2(c00, c00, c02);              \
    add2(c10, c10, c11); add2(c12, c12, c13); add2(c10, c10, c12);              \
    float a0l_, a0h_, a1l_, a1h_;                                               \
    unpk2(a0l_, a0h_, c00);                                                     \
    unpk2(a1l_, a1h_, c10);                                                     \
    ull pcur_ = pp[((T_) - 1) & 3];                                             \
    float mcur_ = mp[((T_) - 1) & 3];                                           \
    if ((T_) + 4 < HT) {                                                        \
        pp[((T_) - 1) & 3] = __ldg(&Pin[(size_t)((T_) + 4) * PSTR + sb + lane]);\
        mp[((T_) - 1) & 3] = __ldg(&g_M[(size_t)((T_) + 4) * HS + s]);          \
    }                                                                           \
    if (RESC_) {                                                                \
        ull rr_ = pk2(rinv_, rinv_);                                            \
        mul2(pcur_, pcur_, rr_);                                                \
        L += lnd_;                                                              \
    }                                                                           \
    L += mcur_;                                                                 \
    upair = pk2(a0l_ + a0h_, a1l_ + a1h_);                                      \
    mul2(upair, upair, pcur_);                                                  \
    reinterpret_cast<ull*>(sm->sv[w][(T_) & 1])[lane] = upair;                  \
    __syncwarp();                                                               \
} while (0)

__device__ void recursion_warp(SmemLayout* sm,
                               const float* __restrict__ trans,
                               const float* __restrict__ initp,
                               float* __restrict__ alpha_out,
                               int write_alpha) {
    int lane = threadIdx.x & 31;
    int w    = (threadIdx.x >> 5) - 4;    // 0..3
    int s    = blockIdx.x * 4 + w;
    int k0 = 2 * lane, k1 = 2 * lane + 1;

    ull Ak0[32], Ak1[32];
    #pragma unroll
    for (int j = 0; j < 32; ++j) {
        Ak0[j] = pk2(__ldg(&trans[(2 * j) * HK + k0]), __ldg(&trans[(2 * j + 1) * HK + k0]));
        Ak1[j] = pk2(__ldg(&trans[(2 * j) * HK + k1]), __ldg(&trans[(2 * j + 1) * HK + k1]));
    }

    const ull* Pin = reinterpret_cast<const ull*>(g_P);
    const int sb   = s * 32;
    const int PSTR = HS * 32;

    // wait t=0..7 ready; preload readiness for 8..11
    #pragma unroll
    for (int j = 0; j < 8; ++j) wait16(j);
    unsigned int rdy[4];
    #pragma unroll
    for (int j = 0; j < 4; ++j) rdy[j] = ld_acq(&g_cnt[8 + j]);

    // t = 0
    ull p0 = __ldg(&Pin[sb + lane]);
    float2 ip = __ldg(reinterpret_cast<const float2*>(initp) + lane);
    ull upair = pk2(ip.x, ip.y);
    mul2(upair, upair, p0);
    reinterpret_cast<ull*>(sm->sv[w][0])[lane] = upair;
    float L = __ldg(&g_M[s]);
    __syncwarp();

    ull pp[4];
    float mp[4];
    #pragma unroll
    for (int j = 0; j < 4; ++j) {
        pp[j] = __ldg(&Pin[(size_t)(1 + j) * PSTR + sb + lane]);
        mp[j] = __ldg(&g_M[(size_t)(1 + j) * HS + s]);
    }

    RC_STEP(1, false);
    RC_STEP(2, false);
    RC_STEP(3, false);

    for (int tb = 4; tb < HT; tb += 4) {
        #pragma unroll
        for (int j = 0; j < 4; ++j) {
            int tt = tb + 4 + j;
            if (tt < HT && rdy[j] < 16u) wait16(tt);
        }
        #pragma unroll
        for (int j = 0; j < 4; ++j) {
            int tt = tb + 8 + j;
            rdy[j] = (tt < HT) ? ld_acq(&g_cnt[tt]) : 16u;
        }
        RC_STEP(tb,     true);
        RC_STEP(tb + 1, false);
        RC_STEP(tb + 2, false);
        RC_STEP(tb + 3, false);
    }

    // final dT
    {
        const ull* vb = reinterpret_cast<const ull*>(sm->sv[w][(HT - 1) & 1]);
        float dT = sum_tree(vb);
        if (write_alpha) {
            ull an = upair;
            float rT = rcpa(dT);
            ull rr = pk2(rT, rT);
            mul2(an, an, rr);
            reinterpret_cast<ull*>(alpha_out)[sb + lane] = an;
        }
        if (lane == 0)
            g_loglik[s] = L + lg2a(dT);
    }
}

// ==================== fused warp-specialized kernel ====================
__global__ void __launch_bounds__(NTHREADS, 1)
hmm_fused(const float* __restrict__ data,
          const float* __restrict__ means,
          const float* __restrict__ covars,
          const float* __restrict__ trans,
          const float* __restrict__ initp,
          float* __restrict__ alpha_out,
          int write_alpha,
          float* __restrict__ scal) {
    __shared__ SmemLayout sm;
    int wid = threadIdx.x >> 5;

    if (wid >= 4)
        recursion_warp(&sm, trans, initp, alpha_out, write_alpha);
    else
        emission_warp(&sm, data, means, covars);

    // CTA-wide join, then fused finalize + state reset by last CTA
    __threadfence();
    __syncthreads();
    __shared__ unsigned int amlast;
    if (threadIdx.x == 0)
        amlast = atomicAdd(&g_done, 1u);
    __syncthreads();
    if (amlast == NCTAS - 1) {
        __threadfence();
        if (scal != nullptr) {
            __shared__ float red[NTHREADS];
            int tid = threadIdx.x;
            red[tid] = g_loglik[tid] + g_loglik[tid + 256];
            __syncthreads();
            for (int st = 128; st > 0; st >>= 1) {
                if (tid < st) red[tid] += red[tid + st];
                __syncthreads();
            }
            if (tid == 0) scal[0] = -red[0] * LN2_F;
        }
        for (int i = threadIdx.x; i < HT; i += NTHREADS)
            g_cnt[i] = 0u;
        if (threadIdx.x == 0) g_done = 0u;
    }
}

extern "C" void kernel_launch(void* const* d_in, const int* in_sizes, int n_in,
                              void* d_out, int out_size) {
    const float* data   = (const float*)d_in[0];
    const float* initp  = (const float*)d_in[1];
    const float* trans  = (const float*)d_in[2];
    const float* means  = (const float*)d_in[3];
    const float* covars = (const float*)d_in[4];
    float* out = (float*)d_out;

    const int AK = HS * HK;  // 32768
    int write_alpha = (out_size >= AK) ? 1 : 0;
    float* scal = nullptr;
    if (out_size == 1)       scal = out;
    else if (out_size > AK)  scal = out + AK;

    hmm_fused<<<NCTAS, NTHREADS>>>(data, means, covars, trans, initp,
                                   out, write_alpha, scal);
}

// round 13
// speedup vs baseline: 1.4339x; 1.4339x over previous
#include <cuda_runtime.h>
#include <cuda_bf16.h>
#include <cstdint>

// HMM forward: T=1024, S=512, D=32, K=64 — best-measured per-phase assembly.
// Emission (R8-proven, ~150us): 4-row-ILP per warp, smem-staged coefficients,
//   max-normalized probs, 4096 CTAs x 128 thr (2/SM).
// Recursion (R7-proven, ~236us): warp-per-sequence, 4 seq/CTA x 128 CTAs,
//   A in registers, rescale every 4 steps via add2 register tree (fits L0 I$),
//   exact log2 telescoping. Scalar finalize fused into last recursion block.

#define HT 1024
#define HS 512
#define HD 32
#define HK 64
#define LOG2PI_F 1.8378770664093453f
#define NEG_HALF_LOG2E -0.72134752044448169f
#define LN2_F 0.69314718055994531f

typedef unsigned long long ull;

__device__ float g_P[(size_t)HT * HS * HK];   // 128 MB normalized emission probs [t][s][k]
__device__ float g_M[(size_t)HT * HS];        // per-(t,s) log2 max
__device__ float g_loglik[HS];
__device__ unsigned int g_done;

__device__ __forceinline__ void fma2(ull& d, ull a, ull b, ull c) {
    asm("fma.rn.f32x2 %0, %1, %2, %3;" : "=l"(d) : "l"(a), "l"(b), "l"(c));
}
__device__ __forceinline__ void add2(ull& d, ull a, ull b) {
    asm("add.rn.f32x2 %0, %1, %2;" : "=l"(d) : "l"(a), "l"(b));
}
__device__ __forceinline__ void mul2(ull& d, ull a, ull b) {
    asm("mul.rn.f32x2 %0, %1, %2;" : "=l"(d) : "l"(a), "l"(b));
}
__device__ __forceinline__ ull pk2(float lo, float hi) {
    ull r;
    asm("mov.b64 %0, {%1, %2};" : "=l"(r) : "f"(lo), "f"(hi));
    return r;
}
__device__ __forceinline__ void unpk2(float& lo, float& hi, ull v) {
    asm("mov.b64 {%0, %1}, %2;" : "=f"(lo), "=f"(hi) : "l"(v));
}
__device__ __forceinline__ float ex2a(float x) {
    float r; asm("ex2.approx.f32 %0, %1;" : "=f"(r) : "f"(x)); return r;
}
__device__ __forceinline__ float lg2a(float x) {
    float r; asm("lg2.approx.f32 %0, %1;" : "=f"(r) : "f"(x)); return r;
}
__device__ __forceinline__ float rcpa(float x) {
    float r; asm("rcp.approx.f32 %0, %1;" : "=f"(r) : "f"(x)); return r;
}

// full-K sum of 32 packed ulls in smem -> scalar (4 chains of 8, no shuffles)
__device__ __forceinline__ float sum_tree(const ull* vb) {
    ull c0 = vb[0], c1 = vb[1], c2 = vb[2], c3 = vb[3];
    #pragma unroll
    for (int j = 1; j < 8; ++j) {
        ull v0 = vb[4 * j], v1 = vb[4 * j + 1], v2 = vb[4 * j + 2], v3 = vb[4 * j + 3];
        add2(c0, c0, v0); add2(c1, c1, v1); add2(c2, c2, v2); add2(c3, c3, v3);
    }
    add2(c0, c0, c1);
    add2(c2, c2, c3);
    add2(c0, c0, c2);
    float lo, hi;
    unpk2(lo, hi, c0);
    return lo + hi;
}

// -------- emission: warp per 32 rows, processed as 8 groups of 4 (ILP=4) --------
#define EM_CTAS 4096
#define EM_THREADS 128

__global__ void __launch_bounds__(EM_THREADS, 2)
hmm_emission(const float* __restrict__ data,
             const float* __restrict__ means,
             const float* __restrict__ covars) {
    __shared__ ull   s_W1[16][HK];
    __shared__ ull   s_W2[16][HK];
    __shared__ float s_pc[16][HK];
    __shared__ float s_C[HK];
    __shared__ __align__(16) float sx[4][2][4][HD];

    int tid  = threadIdx.x;
    int lane = tid & 31;
    int wid  = tid >> 5;
    int gw   = blockIdx.x * (EM_THREADS / 32) + wid;
    int ts0  = gw * 32;

    if (blockIdx.x == 0 && tid == 0) g_done = 0;

    #pragma unroll
    for (int it = 0; it < 8; ++it) {
        int idx = it * EM_THREADS + tid;
        int k  = idx >> 4;
        int dp = idx & 15;
        float2 cv = *reinterpret_cast<const float2*>(&covars[k * HD + 2 * dp]);
        float2 mu = *reinterpret_cast<const float2*>(&means [k * HD + 2 * dp]);
        float iv0 = 1.0f / cv.x, iv1 = 1.0f / cv.y;
        s_W1[dp][k] = pk2(NEG_HALF_LOG2E * iv0, NEG_HALF_LOG2E * iv1);
        s_W2[dp][k] = pk2(NEG_HALF_LOG2E * (-2.0f * mu.x * iv0),
                          NEG_HALF_LOG2E * (-2.0f * mu.y * iv1));
        s_pc[dp][k] = mu.x * mu.x * iv0 + mu.y * mu.y * iv1 + __logf(cv.x) + __logf(cv.y);
    }
    __syncthreads();
    if (tid < HK) {
        float c = (float)HD * LOG2PI_F;
        #pragma unroll
        for (int dp = 0; dp < 16; ++dp) c += s_pc[dp][tid];
        s_C[tid] = NEG_HALF_LOG2E * c;
    }
    __syncthreads();

    ull w1A[16], w2A[16], w1B[16], w2B[16];
    #pragma unroll
    for (int g = 0; g < 16; ++g) {
        ulonglong2 v1 = *reinterpret_cast<const ulonglong2*>(&s_W1[g][2 * lane]);
        ulonglong2 v2 = *reinterpret_cast<const ulonglong2*>(&s_W2[g][2 * lane]);
        w1A[g] = v1.x; w1B[g] = v1.y;
        w2A[g] = v2.x; w2B[g] = v2.y;
    }
    float cA = s_C[2 * lane], cB = s_C[2 * lane + 1];

    float xg[4];
    #pragma unroll
    for (int j = 0; j < 4; ++j)
        xg[j] = __ldg(&data[(size_t)(ts0 + j) * HD + lane]);
    #pragma unroll
    for (int j = 0; j < 4; ++j)
        sx[wid][0][j][lane] = xg[j];
    #pragma unroll
    for (int j = 0; j < 4; ++j)
        xg[j] = __ldg(&data[(size_t)(ts0 + 4 + j) * HD + lane]);
    __syncwarp();

    ull* Pout = reinterpret_cast<ull*>(g_P);

    for (int gq = 0; gq < 8; ++gq) {
        if (gq < 7) {
            #pragma unroll
            for (int j = 0; j < 4; ++j)
                sx[wid][(gq + 1) & 1][j][lane] = xg[j];
            if (gq < 6) {
                #pragma unroll
                for (int j = 0; j < 4; ++j)
                    xg[j] = __ldg(&data[(size_t)(ts0 + (gq + 2) * 4 + j) * HD + lane]);
            }
        }
        __syncwarp();

        const ull* xb0 = reinterpret_cast<const ull*>(sx[wid][gq & 1][0]);
        const ull* xb1 = reinterpret_cast<const ull*>(sx[wid][gq & 1][1]);
        const ull* xb2 = reinterpret_cast<const ull*>(sx[wid][gq & 1][2]);
        const ull* xb3 = reinterpret_cast<const ull*>(sx[wid][gq & 1][3]);

        ull accA[4], accB[4];
        #pragma unroll
        for (int r = 0; r < 4; ++r) { accA[r] = 0ULL; accB[r] = 0ULL; }

        #pragma unroll
        for (int g = 0; g < 16; ++g) {
            ull x0 = xb0[g], x1 = xb1[g], x2 = xb2[g], x3 = xb3[g];
            ull t;
            fma2(t, x0, w1A[g], w2A[g]); fma2(accA[0], x0, t, accA[0]);
            fma2(t, x0, w1B[g], w2B[g]); fma2(accB[0], x0, t, accB[0]);
            fma2(t, x1, w1A[g], w2A[g]); fma2(accA[1], x1, t, accA[1]);
            fma2(t, x1, w1B[g], w2B[g]); fma2(accB[1], x1, t, accB[1]);
            fma2(t, x2, w1A[g], w2A[g]); fma2(accA[2], x2, t, accA[2]);
            fma2(t, x2, w1B[g], w2B[g]); fma2(accB[2], x2, t, accB[2]);
            fma2(t, x3, w1A[g], w2A[g]); fma2(accA[3], x3, t, accA[3]);
            fma2(t, x3, w1B[g], w2B[g]); fma2(accB[3], x3, t, accB[3]);
        }

        float la[4], lb[4], mm[4];
        #pragma unroll
        for (int r = 0; r < 4; ++r) {
            float a0, a1, b0, b1;
            unpk2(a0, a1, accA[r]);
            unpk2(b0, b1, accB[r]);
            la[r] = (a0 + a1) + cA;
            lb[r] = (b0 + b1) + cB;
            mm[r] = fmaxf(la[r], lb[r]);
        }
        #pragma unroll
        for (int off = 16; off; off >>= 1) {
            #pragma unroll
            for (int r = 0; r < 4; ++r)
                mm[r] = fmaxf(mm[r], __shfl_xor_sync(0xffffffffu, mm[r], off));
        }
        #pragma unroll
        for (int r = 0; r < 4; ++r) {
            float pa = ex2a(la[r] - mm[r]);
            float pb = ex2a(lb[r] - mm[r]);
            int ts = ts0 + gq * 4 + r;
            Pout[(size_t)ts * 32 + lane] = pk2(pa, pb);
        }
        if (lane == 0)
            *reinterpret_cast<float4*>(&g_M[ts0 + gq * 4]) =
                make_float4(mm[0], mm[1], mm[2], mm[3]);
        __syncwarp();
    }
}

// -------- recursion: warp-per-sequence, 4/CTA x 128 CTAs; rescale every 4 steps --------
#define RC_BLOCKS (HS / 4)

#define RC_STEP(T_, RESC_) do {                                                 \
    const ull* vb_ = reinterpret_cast<const ull*>(sv[w][((T_) - 1) & 1]);       \
    float rinv_ = 0.0f, lnd_ = 0.0f;                                            \
    if (RESC_) {                                                                \
        float d_ = sum_tree(vb_);                                               \
        rinv_ = rcpa(d_);                                                       \
        lnd_  = lg2a(d_);                                                       \
    }                                                                           \
    ull c00 = 0ULL, c01 = 0ULL, c02 = 0ULL, c03 = 0ULL;                         \
    ull c10 = 0ULL, c11 = 0ULL, c12 = 0ULL, c13 = 0ULL;                         \
    _Pragma("unroll")                                                           \
    for (int j_ = 0; j_ < 8; ++j_) {                                            \
        ull vv_ = vb_[j_];                                                      \
        fma2(c00, vv_, Ak0[j_], c00);                                           \
        fma2(c10, vv_, Ak1[j_], c10);                                           \
    }                                                                           \
    _Pragma("unroll")                                                           \
    for (int j_ = 8; j_ < 16; ++j_) {                                           \
        ull vv_ = vb_[j_];                                                      \
        fma2(c01, vv_, Ak0[j_], c01);                                           \
        fma2(c11, vv_, Ak1[j_], c11);                                           \
    }                                                                           \
    _Pragma("unroll")                                                           \
    for (int j_ = 16; j_ < 24; ++j_) {                                          \
        ull vv_ = vb_[j_];                                                      \
        fma2(c02, vv_, Ak0[j_], c02);                                           \
        fma2(c12, vv_, Ak1[j_], c12);                                           \
    }                                                                           \
    _Pragma("unroll")                                                           \
    for (int j_ = 24; j_ < 32; ++j_) {                                          \
        ull vv_ = vb_[j_];                                                      \
        fma2(c03, vv_, Ak0[j_], c03);                                           \
        fma2(c13, vv_, Ak1[j_], c13);                                           \
    }                                                                           \
    add2(c00, c00, c01); add2(c02, c02, c03); add2(c00, c00, c02);              \
    add2(c10, c10, c11); add2(c12, c12, c13); add2(c10, c10, c12);              \
    float a0l_, a0h_, a1l_, a1h_;                                               \
    unpk2(a0l_, a0h_, c00);                                                     \
    unpk2(a1l_, a1h_, c10);                                                     \
    ull pcur_ = pp[((T_) - 1) & 3];                                             \
    float mcur_ = mp[((T_) - 1) & 3];                                           \
    if ((T_) + 4 < HT) {                                                        \
        pp[((T_) - 1) & 3] = __ldg(&Pin[(size_t)((T_) + 4) * PSTR + sb + lane]);\
        mp[((T_) - 1) & 3] = __ldg(&g_M[(size_t)((T_) + 4) * HS + s]);          \
    }                                                                           \
    if (RESC_) {                                                                \
        ull rr_ = pk2(rinv_, rinv_);                                            \
        mul2(pcur_, pcur_, rr_);                                                \
        L += lnd_;                                                              \
    }                                                                           \
    L += mcur_;                                                                 \
    upair = pk2(a0l_ + a0h_, a1l_ + a1h_);                                      \
    mul2(upair, upair, pcur_);                                                  \
    reinterpret_cast<ull*>(sv[w][(T_) & 1])[lane] = upair;                      \
    __syncwarp();                                                               \
} while (0)

__global__ void __launch_bounds__(128, 1) hmm_recursion(const float* __restrict__ trans,
                                                        const float* __restrict__ initp,
                                                        float* __restrict__ alpha_out,
                                                        int write_alpha,
                                                        float* __restrict__ scal) {
    __shared__ __align__(16) float sv[4][2][HK];
    int lane = threadIdx.x & 31;
    int w    = threadIdx.x >> 5;
    int s    = blockIdx.x * 4 + w;
    int k0 = 2 * lane, k1 = 2 * lane + 1;

    ull Ak0[32], Ak1[32];
    #pragma unroll
    for (int j = 0; j < 32; ++j) {
        Ak0[j] = pk2(__ldg(&trans[(2 * j) * HK + k0]), __ldg(&trans[(2 * j + 1) * HK + k0]));
        Ak1[j] = pk2(__ldg(&trans[(2 * j) * HK + k1]), __ldg(&trans[(2 * j + 1) * HK + k1]));
    }

    const ull* Pin = reinterpret_cast<const ull*>(g_P);
    const int sb   = s * 32;
    const int PSTR = HS * 32;

    // t = 0
    ull p0 = __ldg(&Pin[sb + lane]);
    float2 ip = __ldg(reinterpret_cast<const float2*>(initp) + lane);
    ull upair = pk2(ip.x, ip.y);
    mul2(upair, upair, p0);
    reinterpret_cast<ull*>(sv[w][0])[lane] = upair;
    float L = __ldg(&g_M[s]);
    __syncwarp();

    // prefetch rings for t = 1..4 (slot for step t is (t-1)&3)
    ull pp[4];
    float mp[4];
    #pragma unroll
    for (int j = 0; j < 4; ++j) {
        pp[j] = __ldg(&Pin[(size_t)(1 + j) * PSTR + sb + lane]);
        mp[j] = __ldg(&g_M[(size_t)(1 + j) * HS + s]);
    }

    // prologue t = 1..3 (no rescale)
    RC_STEP(1, false);
    RC_STEP(2, false);
    RC_STEP(3, false);

    // main: chunks of 4, rescale on first step of each chunk
    for (int tb = 4; tb < HT; tb += 4) {
        RC_STEP(tb,     true);
        RC_STEP(tb + 1, false);
        RC_STEP(tb + 2, false);
        RC_STEP(tb + 3, false);
    }

    // final: dT from last buffer
    {
        const ull* vb = reinterpret_cast<const ull*>(sv[w][(HT - 1) & 1]);
        float dT = sum_tree(vb);
        if (write_alpha) {
            ull an = upair;
            float rT = rcpa(dT);
            ull rr = pk2(rT, rT);
            mul2(an, an, rr);
            reinterpret_cast<ull*>(alpha_out)[sb + lane] = an;
        }
        if (lane == 0)
            g_loglik[s] = L + lg2a(dT);
    }

    // fused finalize: release fence -> counter -> acquire fence -> last block reduces
    __threadfence();
    __syncthreads();
    __shared__ unsigned int amlast;
    if (threadIdx.x == 0)
        amlast = atomicAdd(&g_done, 1u);
    __syncthreads();
    if (amlast == RC_BLOCKS - 1 && scal != nullptr) {
        __threadfence();
        __shared__ float red[128];
        int tid = threadIdx.x;
        float acc = g_loglik[tid] + g_loglik[tid + 128]
                  + g_loglik[tid + 256] + g_loglik[tid + 384];
        red[tid] = acc;
        __syncthreads();
        for (int st = 64; st > 0; st >>= 1) {
            if (tid < st) red[tid] += red[tid + st];
            __syncthreads();
        }
        if (tid == 0) scal[0] = -red[0] * LN2_F;
    }
}

extern "C" void kernel_launch(void* const* d_in, const int* in_sizes, int n_in,
                              void* d_out, int out_size) {
    const float* data   = (const float*)d_in[0];
    const float* initp  = (const float*)d_in[1];
    const float* trans  = (const float*)d_in[2];
    const float* means  = (const float*)d_in[3];
    const float* covars = (const float*)d_in[4];
    float* out = (float*)d_out;

    hmm_emission<<<EM_CTAS, EM_THREADS>>>(data, means, covars);

    const int AK = HS * HK;  // 32768
    int write_alpha = (out_size >= AK) ? 1 : 0;
    float* scal = nullptr;
    if (out_size == 1)       scal = out;
    else if (out_size > AK)  scal = out + AK;

    hmm_recursion<<<RC_BLOCKS, 128>>>(trans, initp, out, write_alpha, scal);
}

// round 14
// speedup vs baseline: 1.4778x; 1.0307x over previous
#include <cuda_runtime.h>
#include <cuda_bf16.h>
#include <cstdint>

// HMM forward: T=1024, S=512, D=32, K=64
// Emission v2: 4-row-ILP per warp, coefficients read DIRECTLY from smem in the
//   g-loop (no 128-reg copy) -> ~100 regs -> 4-5 CTAs/SM -> latency hidden.
// Recursion (R7/R13-proven, ~240us): warp-per-sequence, 4 seq/CTA x 128 CTAs,
//   A in registers, rescale every 4 steps, exact log2 telescoping.
//   Scalar finalize fused into last recursion block.

#define HT 1024
#define HS 512
#define HD 32
#define HK 64
#define LOG2PI_F 1.8378770664093453f
#define NEG_HALF_LOG2E -0.72134752044448169f
#define LN2_F 0.69314718055994531f

typedef unsigned long long ull;

__device__ float g_P[(size_t)HT * HS * HK];   // 128 MB normalized emission probs [t][s][k]
__device__ float g_M[(size_t)HT * HS];        // per-(t,s) log2 max
__device__ float g_loglik[HS];
__device__ unsigned int g_done;

__device__ __forceinline__ void fma2(ull& d, ull a, ull b, ull c) {
    asm("fma.rn.f32x2 %0, %1, %2, %3;" : "=l"(d) : "l"(a), "l"(b), "l"(c));
}
__device__ __forceinline__ void add2(ull& d, ull a, ull b) {
    asm("add.rn.f32x2 %0, %1, %2;" : "=l"(d) : "l"(a), "l"(b));
}
__device__ __forceinline__ void mul2(ull& d, ull a, ull b) {
    asm("mul.rn.f32x2 %0, %1, %2;" : "=l"(d) : "l"(a), "l"(b));
}
__device__ __forceinline__ ull pk2(float lo, float hi) {
    ull r;
    asm("mov.b64 %0, {%1, %2};" : "=l"(r) : "f"(lo), "f"(hi));
    return r;
}
__device__ __forceinline__ void unpk2(float& lo, float& hi, ull v) {
    asm("mov.b64 {%0, %1}, %2;" : "=f"(lo), "=f"(hi) : "l"(v));
}
__device__ __forceinline__ float ex2a(float x) {
    float r; asm("ex2.approx.f32 %0, %1;" : "=f"(r) : "f"(x)); return r;
}
__device__ __forceinline__ float lg2a(float x) {
    float r; asm("lg2.approx.f32 %0, %1;" : "=f"(r) : "f"(x)); return r;
}
__device__ __forceinline__ float rcpa(float x) {
    float r; asm("rcp.approx.f32 %0, %1;" : "=f"(r) : "f"(x)); return r;
}

// full-K sum of 32 packed ulls in smem -> scalar (4 chains of 8, no shuffles)
__device__ __forceinline__ float sum_tree(const ull* vb) {
    ull c0 = vb[0], c1 = vb[1], c2 = vb[2], c3 = vb[3];
    #pragma unroll
    for (int j = 1; j < 8; ++j) {
        ull v0 = vb[4 * j], v1 = vb[4 * j + 1], v2 = vb[4 * j + 2], v3 = vb[4 * j + 3];
        add2(c0, c0, v0); add2(c1, c1, v1); add2(c2, c2, v2); add2(c3, c3, v3);
    }
    add2(c0, c0, c1);
    add2(c2, c2, c3);
    add2(c0, c0, c2);
    float lo, hi;
    unpk2(lo, hi, c0);
    return lo + hi;
}

// -------- emission: warp per 32 rows, 8 groups of 4 (ILP=4), W in smem --------
#define EM_CTAS 4096
#define EM_THREADS 128

__global__ void __launch_bounds__(EM_THREADS, 4)
hmm_emission(const float* __restrict__ data,
             const float* __restrict__ means,
             const float* __restrict__ covars) {
    __shared__ ull   s_W1[16][HK];     // 8KB: pk2(NH*iv[k][2g], NH*iv[k][2g+1]), indexed [g][k]
    __shared__ ull   s_W2[16][HK];     // 8KB
    __shared__ float s_pc[16][HK];     // 4KB partial c
    __shared__ float s_C[HK];
    __shared__ __align__(16) float sx[4][2][4][HD];

    int tid  = threadIdx.x;
    int lane = tid & 31;
    int wid  = tid >> 5;
    int gw   = blockIdx.x * (EM_THREADS / 32) + wid;
    int ts0  = gw * 32;

    if (blockIdx.x == 0 && tid == 0) g_done = 0;

    #pragma unroll
    for (int it = 0; it < 8; ++it) {
        int idx = it * EM_THREADS + tid;
        int k  = idx >> 4;
        int dp = idx & 15;
        float2 cv = *reinterpret_cast<const float2*>(&covars[k * HD + 2 * dp]);
        float2 mu = *reinterpret_cast<const float2*>(&means [k * HD + 2 * dp]);
        float iv0 = 1.0f / cv.x, iv1 = 1.0f / cv.y;
        s_W1[dp][k] = pk2(NEG_HALF_LOG2E * iv0, NEG_HALF_LOG2E * iv1);
        s_W2[dp][k] = pk2(NEG_HALF_LOG2E * (-2.0f * mu.x * iv0),
                          NEG_HALF_LOG2E * (-2.0f * mu.y * iv1));
        s_pc[dp][k] = mu.x * mu.x * iv0 + mu.y * mu.y * iv1 + __logf(cv.x) + __logf(cv.y);
    }
    __syncthreads();
    if (tid < HK) {
        float c = (float)HD * LOG2PI_F;
        #pragma unroll
        for (int dp = 0; dp < 16; ++dp) c += s_pc[dp][tid];
        s_C[tid] = NEG_HALF_LOG2E * c;
    }
    __syncthreads();

    float cA = s_C[2 * lane], cB = s_C[2 * lane + 1];

    float xg[4];
    #pragma unroll
    for (int j = 0; j < 4; ++j)
        xg[j] = __ldg(&data[(size_t)(ts0 + j) * HD + lane]);
    #pragma unroll
    for (int j = 0; j < 4; ++j)
        sx[wid][0][j][lane] = xg[j];
    #pragma unroll
    for (int j = 0; j < 4; ++j)
        xg[j] = __ldg(&data[(size_t)(ts0 + 4 + j) * HD + lane]);
    __syncwarp();

    ull* Pout = reinterpret_cast<ull*>(g_P);

    for (int gq = 0; gq < 8; ++gq) {
        if (gq < 7) {
            #pragma unroll
            for (int j = 0; j < 4; ++j)
                sx[wid][(gq + 1) & 1][j][lane] = xg[j];
            if (gq < 6) {
                #pragma unroll
                for (int j = 0; j < 4; ++j)
                    xg[j] = __ldg(&data[(size_t)(ts0 + (gq + 2) * 4 + j) * HD + lane]);
            }
        }
        __syncwarp();

        const ull* xb0 = reinterpret_cast<const ull*>(sx[wid][gq & 1][0]);
        const ull* xb1 = reinterpret_cast<const ull*>(sx[wid][gq & 1][1]);
        const ull* xb2 = reinterpret_cast<const ull*>(sx[wid][gq & 1][2]);
        const ull* xb3 = reinterpret_cast<const ull*>(sx[wid][gq & 1][3]);

        ull accA[4], accB[4];
        #pragma unroll
        for (int r = 0; r < 4; ++r) { accA[r] = 0ULL; accB[r] = 0ULL; }

        #pragma unroll
        for (int g = 0; g < 16; ++g) {
            // coefficients straight from smem (conflict-free LDS.128, 16B/lane stride)
            ulonglong2 v1 = *reinterpret_cast<const ulonglong2*>(&s_W1[g][2 * lane]);
            ulonglong2 v2 = *reinterpret_cast<const ulonglong2*>(&s_W2[g][2 * lane]);
            ull w1A = v1.x, w1B = v1.y;
            ull w2A = v2.x, w2B = v2.y;
            ull x0 = xb0[g], x1 = xb1[g], x2 = xb2[g], x3 = xb3[g];
            ull t;
            fma2(t, x0, w1A, w2A); fma2(accA[0], x0, t, accA[0]);
            fma2(t, x0, w1B, w2B); fma2(accB[0], x0, t, accB[0]);
            fma2(t, x1, w1A, w2A); fma2(accA[1], x1, t, accA[1]);
            fma2(t, x1, w1B, w2B); fma2(accB[1], x1, t, accB[1]);
            fma2(t, x2, w1A, w2A); fma2(accA[2], x2, t, accA[2]);
            fma2(t, x2, w1B, w2B); fma2(accB[2], x2, t, accB[2]);
            fma2(t, x3, w1A, w2A); fma2(accA[3], x3, t, accA[3]);
            fma2(t, x3, w1B, w2B); fma2(accB[3], x3, t, accB[3]);
        }

        float la[4], lb[4], mm[4];
        #pragma unroll
        for (int r = 0; r < 4; ++r) {
            float a0, a1, b0, b1;
            unpk2(a0, a1, accA[r]);
            unpk2(b0, b1, accB[r]);
            la[r] = (a0 + a1) + cA;
            lb[r] = (b0 + b1) + cB;
            mm[r] = fmaxf(la[r], lb[r]);
        }
        #pragma unroll
        for (int off = 16; off; off >>= 1) {
            #pragma unroll
            for (int r = 0; r < 4; ++r)
                mm[r] = fmaxf(mm[r], __shfl_xor_sync(0xffffffffu, mm[r], off));
        }
        #pragma unroll
        for (int r = 0; r < 4; ++r) {
            float pa = ex2a(la[r] - mm[r]);
            float pb = ex2a(lb[r] - mm[r]);
            int ts = ts0 + gq * 4 + r;
            Pout[(size_t)ts * 32 + lane] = pk2(pa, pb);
        }
        if (lane == 0)
            *reinterpret_cast<float4*>(&g_M[ts0 + gq * 4]) =
                make_float4(mm[0], mm[1], mm[2], mm[3]);
        __syncwarp();
    }
}

// -------- recursion: warp-per-sequence, 4/CTA x 128 CTAs; rescale every 4 steps --------
#define RC_BLOCKS (HS / 4)

#define RC_STEP(T_, RESC_) do {                                                 \
    const ull* vb_ = reinterpret_cast<const ull*>(sv[w][((T_) - 1) & 1]);       \
    float rinv_ = 0.0f, lnd_ = 0.0f;                                            \
    if (RESC_) {                                                                \
        float d_ = sum_tree(vb_);                                               \
        rinv_ = rcpa(d_);                                                       \
        lnd_  = lg2a(d_);                                                       \
    }                                                                           \
    ull c00 = 0ULL, c01 = 0ULL, c02 = 0ULL, c03 = 0ULL;                         \
    ull c10 = 0ULL, c11 = 0ULL, c12 = 0ULL, c13 = 0ULL;                         \
    _Pragma("unroll")                                                           \
    for (int j_ = 0; j_ < 8; ++j_) {                                            \
        ull vv_ = vb_[j_];                                                      \
        fma2(c00, vv_, Ak0[j_], c00);                                           \
        fma2(c10, vv_, Ak1[j_], c10);                                           \
    }                                                                           \
    _Pragma("unroll")                                                           \
    for (int j_ = 8; j_ < 16; ++j_) {                                           \
        ull vv_ = vb_[j_];                                                      \
        fma2(c01, vv_, Ak0[j_], c01);                                           \
        fma2(c11, vv_, Ak1[j_], c11);                                           \
    }                                                                           \
    _Pragma("unroll")                                                           \
    for (int j_ = 16; j_ < 24; ++j_) {                                          \
        ull vv_ = vb_[j_];                                                      \
        fma2(c02, vv_, Ak0[j_], c02);                                           \
        fma2(c12, vv_, Ak1[j_], c12);                                           \
    }                                                                           \
    _Pragma("unroll")                                                           \
    for (int j_ = 24; j_ < 32; ++j_) {                                          \
        ull vv_ = vb_[j_];                                                      \
        fma2(c03, vv_, Ak0[j_], c03);                                           \
        fma2(c13, vv_, Ak1[j_], c13);                                           \
    }                                                                           \
    add2(c00, c00, c01); add2(c02, c02, c03); add2(c00, c00, c02);              \
    add2(c10, c10, c11); add2(c12, c12, c13); add2(c10, c10, c12);              \
    float a0l_, a0h_, a1l_, a1h_;                                               \
    unpk2(a0l_, a0h_, c00);                                                     \
    unpk2(a1l_, a1h_, c10);                                                     \
    ull pcur_ = pp[((T_) - 1) & 3];                                             \
    float mcur_ = mp[((T_) - 1) & 3];                                           \
    if ((T_) + 4 < HT) {                                                        \
        pp[((T_) - 1) & 3] = __ldg(&Pin[(size_t)((T_) + 4) * PSTR + sb + lane]);\
        mp[((T_) - 1) & 3] = __ldg(&g_M[(size_t)((T_) + 4) * HS + s]);          \
    }                                                                           \
    if (RESC_) {                                                                \
        ull rr_ = pk2(rinv_, rinv_);                                            \
        mul2(pcur_, pcur_, rr_);                                                \
        L += lnd_;                                                              \
    }                                                                           \
    L += mcur_;                                                                 \
    upair = pk2(a0l_ + a0h_, a1l_ + a1h_);                                      \
    mul2(upair, upair, pcur_);                                                  \
    reinterpret_cast<ull*>(sv[w][(T_) & 1])[lane] = upair;                      \
    __syncwarp();                                                               \
} while (0)

__global__ void __launch_bounds__(128, 1) hmm_recursion(const float* __restrict__ trans,
                                                        const float* __restrict__ initp,
                                                        float* __restrict__ alpha_out,
                                                        int write_alpha,
                                                        float* __restrict__ scal) {
    __shared__ __align__(16) float sv[4][2][HK];
    int lane = threadIdx.x & 31;
    int w    = threadIdx.x >> 5;
    int s    = blockIdx.x * 4 + w;
    int k0 = 2 * lane, k1 = 2 * lane + 1;

    ull Ak0[32], Ak1[32];
    #pragma unroll
    for (int j = 0; j < 32; ++j) {
        Ak0[j] = pk2(__ldg(&trans[(2 * j) * HK + k0]), __ldg(&trans[(2 * j + 1) * HK + k0]));
        Ak1[j] = pk2(__ldg(&trans[(2 * j) * HK + k1]), __ldg(&trans[(2 * j + 1) * HK + k1]));
    }

    const ull* Pin = reinterpret_cast<const ull*>(g_P);
    const int sb   = s * 32;
    const int PSTR = HS * 32;

    // t = 0
    ull p0 = __ldg(&Pin[sb + lane]);
    float2 ip = __ldg(reinterpret_cast<const float2*>(initp) + lane);
    ull upair = pk2(ip.x, ip.y);
    mul2(upair, upair, p0);
    reinterpret_cast<ull*>(sv[w][0])[lane] = upair;
    float L = __ldg(&g_M[s]);
    __syncwarp();

    // prefetch rings for t = 1..4 (slot for step t is (t-1)&3)
    ull pp[4];
    float mp[4];
    #pragma unroll
    for (int j = 0; j < 4; ++j) {
        pp[j] = __ldg(&Pin[(size_t)(1 + j) * PSTR + sb + lane]);
        mp[j] = __ldg(&g_M[(size_t)(1 + j) * HS + s]);
    }

    // prologue t = 1..3 (no rescale)
    RC_STEP(1, false);
    RC_STEP(2, false);
    RC_STEP(3, false);

    // main: chunks of 4, rescale on first step of each chunk
    for (int tb = 4; tb < HT; tb += 4) {
        RC_STEP(tb,     true);
        RC_STEP(tb + 1, false);
        RC_STEP(tb + 2, false);
        RC_STEP(tb + 3, false);
    }

    // final: dT from last buffer
    {
        const ull* vb = reinterpret_cast<const ull*>(sv[w][(HT - 1) & 1]);
        float dT = sum_tree(vb);
        if (write_alpha) {
            ull an = upair;
            float rT = rcpa(dT);
            ull rr = pk2(rT, rT);
            mul2(an, an, rr);
            reinterpret_cast<ull*>(alpha_out)[sb + lane] = an;
        }
        if (lane == 0)
            g_loglik[s] = L + lg2a(dT);
    }

    // fused finalize: release fence -> counter -> acquire fence -> last block reduces
    __threadfence();
    __syncthreads();
    __shared__ unsigned int amlast;
    if (threadIdx.x == 0)
        amlast = atomicAdd(&g_done, 1u);
    __syncthreads();
    if (amlast == RC_BLOCKS - 1 && scal != nullptr) {
        __threadfence();
        __shared__ float red[128];
        int tid = threadIdx.x;
        float acc = g_loglik[tid] + g_loglik[tid + 128]
                  + g_loglik[tid + 256] + g_loglik[tid + 384];
        red[tid] = acc;
        __syncthreads();
        for (int st = 64; st > 0; st >>= 1) {
            if (tid < st) red[tid] += red[tid + st];
            __syncthreads();
        }
        if (tid == 0) scal[0] = -red[0] * LN2_F;
    }
}

extern "C" void kernel_launch(void* const* d_in, const int* in_sizes, int n_in,
                              void* d_out, int out_size) {
    const float* data   = (const float*)d_in[0];
    const float* initp  = (const float*)d_in[1];
    const float* trans  = (const float*)d_in[2];
    const float* means  = (const float*)d_in[3];
    const float* covars = (const float*)d_in[4];
    float* out = (float*)d_out;

    hmm_emission<<<EM_CTAS, EM_THREADS>>>(data, means, covars);

    const int AK = HS * HK;  // 32768
    int write_alpha = (out_size >= AK) ? 1 : 0;
    float* scal = nullptr;
    if (out_size == 1)       scal = out;
    else if (out_size > AK)  scal = out + AK;

    hmm_recursion<<<RC_BLOCKS, 128>>>(trans, initp, out, write_alpha, scal);
}